// round 13
// baseline (speedup 1.0000x reference)
#include <cuda_runtime.h>
#include <cuda_fp16.h>
#include <cstdint>

#define N_NODES 100000
#define D_FEAT  128
#define N_EDGES 1600000
#define SCAN_B  512
#define SCAN_NB ((N_NODES + SCAN_B - 1) / SCAN_B)   // 196

// ---------------- scratch (device globals; no allocations allowed) ----------
__device__ float  g_k[(size_t)N_NODES * D_FEAT];
__device__ __half g_qvh[(size_t)N_NODES * 256];     // per node: 128 q | 128 v
__device__ float  g_agg[(size_t)N_NODES * D_FEAT];  // skip term from GEMM
__device__ float  g_x[(size_t)N_NODES * D_FEAT];
__device__ float  g_k3[N_NODES];
__device__ float  g_q3[N_NODES];
__device__ float  g_v3[N_NODES];
// CSR sort scratch
__device__ int g_cnt[N_NODES];
__device__ int g_cursor[N_NODES];
__device__ int g_rowptr[N_NODES];
__device__ int g_blocksum[SCAN_NB];
__device__ int g_ssrc[N_EDGES];

// ---------------- f32x2 helpers (sm_100+ packed fp32; 2x FFMA throughput) ---
__device__ __forceinline__ unsigned long long pack2(float x) {
    unsigned long long r;
    asm("mov.b64 %0, {%1, %1};" : "=l"(r) : "f"(x));
    return r;
}
__device__ __forceinline__ unsigned long long fma2(unsigned long long a,
                                                   unsigned long long b,
                                                   unsigned long long c) {
    unsigned long long d;
    asm("fma.rn.f32x2 %0, %1, %2, %3;" : "=l"(d) : "l"(a), "l"(b), "l"(c));
    return d;
}
__device__ __forceinline__ void unpack2(unsigned long long v, float& lo, float& hi) {
    asm("mov.b64 {%0, %1}, %2;" : "=f"(lo), "=f"(hi) : "l"(v));
}
// sigmoid(x) = 0.5*tanh(x/2) + 0.5  -- single MUFU.TANH (sm_75+)
__device__ __forceinline__ float sigf(float x) {
    float t;
    asm("tanh.approx.f32 %0, %1;" : "=f"(t) : "f"(x * 0.5f));
    return fmaf(0.5f, t, 0.5f);
}

// ================= counting sort by dst =====================================
__global__ void zero_kernel() {
    int i = blockIdx.x * blockDim.x + threadIdx.x;
    if (i < N_NODES) { g_cnt[i] = 0; g_cursor[i] = 0; }
}
__global__ void hist_kernel(const int* __restrict__ dst, int E) {
    int e = blockIdx.x * blockDim.x + threadIdx.x;
    if (e < E) atomicAdd(&g_cnt[dst[e]], 1);
}
__global__ void scan1_kernel() {
    __shared__ int sh[SCAN_B];
    int t = threadIdx.x;
    int i = blockIdx.x * SCAN_B + t;
    int v = (i < N_NODES) ? g_cnt[i] : 0;
    sh[t] = v;
    __syncthreads();
#pragma unroll
    for (int off = 1; off < SCAN_B; off <<= 1) {
        int add = (t >= off) ? sh[t - off] : 0;
        __syncthreads();
        sh[t] += add;
        __syncthreads();
    }
    if (i < N_NODES) g_rowptr[i] = sh[t] - v;
    if (t == SCAN_B - 1) g_blocksum[blockIdx.x] = sh[t];
}
__global__ void scan2_kernel() {
    __shared__ int sh[256];
    int t = threadIdx.x;
    int v = (t < SCAN_NB) ? g_blocksum[t] : 0;
    sh[t] = v;
    __syncthreads();
#pragma unroll
    for (int off = 1; off < 256; off <<= 1) {
        int add = (t >= off) ? sh[t - off] : 0;
        __syncthreads();
        sh[t] += add;
        __syncthreads();
    }
    if (t < SCAN_NB) g_blocksum[t] = sh[t] - v;
}
__global__ void scan3_kernel() {
    int i = blockIdx.x * blockDim.x + threadIdx.x;
    if (i < N_NODES) g_rowptr[i] += g_blocksum[i / SCAN_B];
}
__global__ void scatter_kernel(const int* __restrict__ src,
                               const int* __restrict__ dst, int E) {
    int e = blockIdx.x * blockDim.x + threadIdx.x;
    if (e < E) {
        int d = dst[e];
        int pos = g_rowptr[d] + atomicAdd(&g_cursor[d], 1);
        g_ssrc[pos] = src[e];
    }
}

// ================= fused 4-matrix GEMM ======================================
// {k,q,v,skip} = X @ {Wk,Wq,Wv,Ws}(+b). BM=64, BN=64 (half-matrix per
// blockIdx.y of 8). 128 threads, thread tile 4 rows x 8 cols, X register-
// cached, X chunks software-pipelined. k,skip -> fp32; q,v -> fp16 (g_qvh).
#define GBM 64
#define XCH 32
#define XST 36

__global__ void gemm4_kernel(const float* __restrict__ X,
                             const float* __restrict__ Wk,
                             const float* __restrict__ Wq,
                             const float* __restrict__ Wv,
                             const float* __restrict__ Ws,
                             const float* __restrict__ bias,
                             int M) {
    __shared__ float Wsm[128 * 64];
    __shared__ float Xs[GBM * XST];

    const float* Xp = X ? X : g_x;

    const int m0   = blockIdx.x * GBM;
    const int bn   = blockIdx.y;
    const int mat  = bn >> 1;
    const int noff = (bn & 1) * 64;

    const float* W = (mat == 0) ? Wk : (mat == 1) ? Wq : (mat == 2) ? Wv : Ws;

    const int tid = threadIdx.x;        // 0..127
    const int ty  = tid >> 3;           // 0..15 -> rows ty + 16*i
    const int tx  = tid & 7;            // 0..7  -> cols tx*8 .. tx*8+7

    // Load W half [128][64] (float4, coalesced)
    for (int i = tid; i < 128 * 16; i += 128) {
        int k = i >> 4, n4 = i & 15;
        *(float4*)(Wsm + k * 64 + n4 * 4) =
            *(const float4*)(W + k * 128 + noff + n4 * 4);
    }

    // Per-thread X-staging: 4 float4 (rows tid>>3 strided, cols tid&7)
    const int lr = tid >> 5;            // 0..3 -> rows lr + 4*u (u=0..15)? no:
    // each thread loads 4 float4: linear ids tid, tid+128, tid+256, tid+384
    float4 stage[4];
#pragma unroll
    for (int u = 0; u < 4; u++) {
        int i = tid + u * 128;          // 0..511
        int r = i >> 3, c4 = i & 7;
        stage[u] = make_float4(0.f, 0.f, 0.f, 0.f);
        if (m0 + r < M)
            stage[u] = *(const float4*)(Xp + (size_t)(m0 + r) * 128 + c4 * 4);
    }

    unsigned long long acc[4][4];
#pragma unroll
    for (int i = 0; i < 4; i++)
#pragma unroll
        for (int j = 0; j < 4; j++) acc[i][j] = 0ULL;

    for (int ch = 0; ch < 128 / XCH; ch++) {
        __syncthreads();
        // store staged chunk to smem
#pragma unroll
        for (int u = 0; u < 4; u++) {
            int i = tid + u * 128;
            int r = i >> 3, c4 = i & 7;
            *(float4*)(Xs + r * XST + c4 * 4) = stage[u];
        }
        __syncthreads();
        // prefetch next chunk (overlaps with FMA loop below)
        if (ch + 1 < 128 / XCH) {
#pragma unroll
            for (int u = 0; u < 4; u++) {
                int i = tid + u * 128;
                int r = i >> 3, c4 = i & 7;
                stage[u] = make_float4(0.f, 0.f, 0.f, 0.f);
                if (m0 + r < M)
                    stage[u] = *(const float4*)(Xp + (size_t)(m0 + r) * 128 +
                                                (ch + 1) * XCH + c4 * 4);
            }
        }
        (void)lr;

#pragma unroll
        for (int kk4 = 0; kk4 < XCH / 4; kk4++) {
            float xa[4][4];
#pragma unroll
            for (int i = 0; i < 4; i++) {
                float4 xv = *(const float4*)(Xs + (ty + 16 * i) * XST + kk4 * 4);
                xa[i][0] = xv.x; xa[i][1] = xv.y; xa[i][2] = xv.z; xa[i][3] = xv.w;
            }
#pragma unroll
            for (int j = 0; j < 4; j++) {
                const unsigned long long* wp = (const unsigned long long*)
                    (Wsm + (ch * XCH + kk4 * 4 + j) * 64 + tx * 8);
                unsigned long long b0 = wp[0], b1 = wp[1], b2 = wp[2], b3 = wp[3];
#pragma unroll
                for (int i = 0; i < 4; i++) {
                    unsigned long long aa = pack2(xa[i][j]);
                    acc[i][0] = fma2(aa, b0, acc[i][0]);
                    acc[i][1] = fma2(aa, b1, acc[i][1]);
                    acc[i][2] = fma2(aa, b2, acc[i][2]);
                    acc[i][3] = fma2(aa, b3, acc[i][3]);
                }
            }
        }
    }

    const int col = noff + tx * 8;
    float bb[8];
#pragma unroll
    for (int j = 0; j < 8; j++) bb[j] = 0.f;
    if (mat == 3) {
#pragma unroll
        for (int j = 0; j < 8; j++) bb[j] = bias[col + j];
    }
#pragma unroll
    for (int i = 0; i < 4; i++) {
        int r = m0 + ty + 16 * i;
        if (r >= M) continue;
        float o[8];
        unpack2(acc[i][0], o[0], o[1]);
        unpack2(acc[i][1], o[2], o[3]);
        unpack2(acc[i][2], o[4], o[5]);
        unpack2(acc[i][3], o[6], o[7]);
        if (mat == 0 || mat == 3) {
            float* Op = (mat == 0) ? g_k : g_agg;
            *(float4*)(Op + (size_t)r * 128 + col) =
                make_float4(o[0] + bb[0], o[1] + bb[1], o[2] + bb[2], o[3] + bb[3]);
            *(float4*)(Op + (size_t)r * 128 + col + 4) =
                make_float4(o[4] + bb[4], o[5] + bb[5], o[6] + bb[6], o[7] + bb[7]);
        } else {
            // q -> halves [0,128), v -> halves [128,256) of the packed row
            __half2 h0 = __floats2half2_rn(o[0], o[1]);
            __half2 h1 = __floats2half2_rn(o[2], o[3]);
            __half2 h2 = __floats2half2_rn(o[4], o[5]);
            __half2 h3 = __floats2half2_rn(o[6], o[7]);
            uint4 u = make_uint4(*(uint32_t*)&h0, *(uint32_t*)&h1,
                                 *(uint32_t*)&h2, *(uint32_t*)&h3);
            size_t hoff = (size_t)r * 256 + ((mat == 2) ? 128 : 0) + col;
            *(uint4*)(g_qvh + hoff) = u;
        }
    }
}

// ================= per-dst aggregation (CSR, no atomics, fp16 gathers) ======
// One warp per destination node; lane j handles features 4j..4j+3.
// 8-edge batches, loads issued before compute (MLP=16 per lane).
__device__ __forceinline__ void qv_load(int s, int lane, uint2& qu, uint2& vu) {
    qu = *((const uint2*)(g_qvh + (size_t)s * 256) + lane);
    vu = *((const uint2*)(g_qvh + (size_t)s * 256 + 128) + lane);
}
__device__ __forceinline__ void qv_accum(const uint2& qu, const uint2& vu,
                                         const float4& kk, float4& acc) {
    float2 q01 = __half22float2(*(const __half2*)&qu.x);
    float2 q23 = __half22float2(*(const __half2*)&qu.y);
    float2 v01 = __half22float2(*(const __half2*)&vu.x);
    float2 v23 = __half22float2(*(const __half2*)&vu.y);
    acc.x += v01.x * sigf(kk.x + q01.x);
    acc.y += v01.y * sigf(kk.y + q01.y);
    acc.z += v23.x * sigf(kk.z + q23.x);
    acc.w += v23.y * sigf(kk.w + q23.y);
}

__global__ void agg_kernel(int relu_flag) {
    int w = (blockIdx.x * blockDim.x + threadIdx.x) >> 5;
    int lane = threadIdx.x & 31;
    if (w >= N_NODES) return;

    float4 kk = *(const float4*)(g_k + (size_t)w * 128 + lane * 4);
    int start = g_rowptr[w];
    int len   = g_cnt[w];

    float4 acc = make_float4(0.f, 0.f, 0.f, 0.f);
    int i = 0;
    for (; i + 8 <= len; i += 8) {
        int s[8];
#pragma unroll
        for (int j = 0; j < 8; j++) s[j] = g_ssrc[start + i + j];
        uint2 qu[8], vu[8];
#pragma unroll
        for (int j = 0; j < 8; j++) qv_load(s[j], lane, qu[j], vu[j]);
#pragma unroll
        for (int j = 0; j < 8; j++) qv_accum(qu[j], vu[j], kk, acc);
    }
    for (; i < len; i++) {
        uint2 qu, vu;
        qv_load(g_ssrc[start + i], lane, qu, vu);
        qv_accum(qu, vu, kk, acc);
    }

    float4 skip = *(const float4*)(g_agg + (size_t)w * 128 + lane * 4);
    float4 r = make_float4(skip.x + acc.x, skip.y + acc.y,
                           skip.z + acc.z, skip.w + acc.w);
    if (relu_flag) {
        r.x = fmaxf(r.x, 0.f); r.y = fmaxf(r.y, 0.f);
        r.z = fmaxf(r.z, 0.f); r.w = fmaxf(r.w, 0.f);
    }
    *(float4*)(g_x + (size_t)w * 128 + lane * 4) = r;
}

// ================= layer 3 (Dout=1) =========================================
__global__ void gemm3_kernel(const float* __restrict__ Wk,
                             const float* __restrict__ Wq,
                             const float* __restrict__ Wv,
                             const float* __restrict__ Ws,
                             const float* __restrict__ bias,
                             float* __restrict__ out,
                             int Nn) {
    int warp = (blockIdx.x * blockDim.x + threadIdx.x) >> 5;
    int lane = threadIdx.x & 31;
    if (warp >= Nn) return;

    float4 xv = *(const float4*)(g_x + (size_t)warp * 128 + lane * 4);
    float4 wk = ((const float4*)Wk)[lane];
    float4 wq = ((const float4*)Wq)[lane];
    float4 wv = ((const float4*)Wv)[lane];
    float4 ws = ((const float4*)Ws)[lane];

    float dk = xv.x * wk.x + xv.y * wk.y + xv.z * wk.z + xv.w * wk.w;
    float dq = xv.x * wq.x + xv.y * wq.y + xv.z * wq.z + xv.w * wq.w;
    float dv = xv.x * wv.x + xv.y * wv.y + xv.z * wv.z + xv.w * wv.w;
    float ds = xv.x * ws.x + xv.y * ws.y + xv.z * ws.z + xv.w * ws.w;

#pragma unroll
    for (int o = 16; o; o >>= 1) {
        dk += __shfl_xor_sync(0xFFFFFFFFu, dk, o);
        dq += __shfl_xor_sync(0xFFFFFFFFu, dq, o);
        dv += __shfl_xor_sync(0xFFFFFFFFu, dv, o);
        ds += __shfl_xor_sync(0xFFFFFFFFu, ds, o);
    }
    if (lane == 0) {
        g_k3[warp] = dk;
        g_q3[warp] = dq;
        g_v3[warp] = dv;
        out[warp]  = ds + bias[0];
    }
}

__global__ void edge3_kernel(float* __restrict__ out) {
    int d = blockIdx.x * blockDim.x + threadIdx.x;
    if (d >= N_NODES) return;
    int start = g_rowptr[d];
    int len   = g_cnt[d];
    float kd = g_k3[d];
    float s = 0.f;
    for (int i = 0; i < len; i++) {
        int sn = g_ssrc[start + i];
        s += g_v3[sn] * sigf(kd + g_q3[sn]);
    }
    out[d] += s;
}

// ================= launch ===================================================
extern "C" void kernel_launch(void* const* d_in, const int* in_sizes, int n_in,
                              void* d_out, int out_size) {
    const float* x  = (const float*)d_in[0];
    const int*   ei = (const int*)d_in[1];
    const int E = in_sizes[1] / 2;
    const int N = in_sizes[0] / D_FEAT;
    const int* src = ei;
    const int* dst = ei + E;

    const float* Wk1 = (const float*)d_in[2];
    const float* Wq1 = (const float*)d_in[3];
    const float* Wv1 = (const float*)d_in[4];
    const float* Ws1 = (const float*)d_in[5];
    const float* b1  = (const float*)d_in[6];
    const float* Wk2 = (const float*)d_in[7];
    const float* Wq2 = (const float*)d_in[8];
    const float* Wv2 = (const float*)d_in[9];
    const float* Ws2 = (const float*)d_in[10];
    const float* b2  = (const float*)d_in[11];
    const float* Wk3 = (const float*)d_in[12];
    const float* Wq3 = (const float*)d_in[13];
    const float* Wv3 = (const float*)d_in[14];
    const float* Ws3 = (const float*)d_in[15];
    const float* b3  = (const float*)d_in[16];

    float* out = (float*)d_out;

    dim3 gemm_grid((N + GBM - 1) / GBM, 8);
    int nblk256 = (N_NODES + 255) / 256;
    int eblk256 = (E + 255) / 256;
    int agg_blocks  = (N + 7) / 8;
    int gemv_blocks = (N + 7) / 8;

    // ---- build dst-sorted CSR (once per call, reused by 3 edge passes) ----
    zero_kernel<<<nblk256, 256>>>();
    hist_kernel<<<eblk256, 256>>>(dst, E);
    scan1_kernel<<<SCAN_NB, SCAN_B>>>();
    scan2_kernel<<<1, 256>>>();
    scan3_kernel<<<nblk256, 256>>>();
    scatter_kernel<<<eblk256, 256>>>(src, dst, E);

    // ---- layer 1 ----
    gemm4_kernel<<<gemm_grid, 128>>>(x, Wk1, Wq1, Wv1, Ws1, b1, N);
    agg_kernel<<<agg_blocks, 256>>>(1);

    // ---- layer 2 (X = nullptr -> kernel reads g_x device-side) ----
    gemm4_kernel<<<gemm_grid, 128>>>(nullptr, Wk2, Wq2, Wv2, Ws2, b2, N);
    agg_kernel<<<agg_blocks, 256>>>(1);

    // ---- layer 3 (Dout=1) ----
    gemm3_kernel<<<gemv_blocks, 256>>>(Wk3, Wq3, Wv3, Ws3, b3, out, N);
    edge3_kernel<<<nblk256, 256>>>(out);
}

// round 15
// speedup vs baseline: 1.0430x; 1.0430x over previous
#include <cuda_runtime.h>
#include <cuda_fp16.h>
#include <cstdint>

#define N_NODES 100000
#define D_FEAT  128
#define N_EDGES 1600000
#define SCAN_B  512
#define SCAN_NB ((N_NODES + SCAN_B - 1) / SCAN_B)   // 196

// ---------------- scratch (device globals; no allocations allowed) ----------
__device__ float  g_k[(size_t)N_NODES * D_FEAT];
__device__ __half g_qvh[(size_t)N_NODES * 256];     // per node: 128 q | 128 v
__device__ float  g_agg[(size_t)N_NODES * D_FEAT];  // skip term from GEMM
__device__ float  g_x[(size_t)N_NODES * D_FEAT];
__device__ float  g_k3[N_NODES];
__device__ float  g_q3[N_NODES];
__device__ float  g_v3[N_NODES];
// CSR sort scratch
__device__ int g_cnt[N_NODES];
__device__ int g_cursor[N_NODES];
__device__ int g_rowptr[N_NODES];
__device__ int g_blocksum[SCAN_NB];
__device__ int g_ssrc[N_EDGES];

// ---------------- f32x2 helpers (sm_100+ packed fp32; 2x FFMA throughput) ---
__device__ __forceinline__ unsigned long long pack2(float x) {
    unsigned long long r;
    asm("mov.b64 %0, {%1, %1};" : "=l"(r) : "f"(x));
    return r;
}
__device__ __forceinline__ unsigned long long fma2(unsigned long long a,
                                                   unsigned long long b,
                                                   unsigned long long c) {
    unsigned long long d;
    asm("fma.rn.f32x2 %0, %1, %2, %3;" : "=l"(d) : "l"(a), "l"(b), "l"(c));
    return d;
}
__device__ __forceinline__ void unpack2(unsigned long long v, float& lo, float& hi) {
    asm("mov.b64 {%0, %1}, %2;" : "=f"(lo), "=f"(hi) : "l"(v));
}
// sigmoid(x) = 0.5*tanh(x/2) + 0.5  -- single MUFU.TANH (sm_75+)
__device__ __forceinline__ float sigf(float x) {
    float t;
    asm("tanh.approx.f32 %0, %1;" : "=f"(t) : "f"(x * 0.5f));
    return fmaf(0.5f, t, 0.5f);
}

// ================= counting sort by dst =====================================
__global__ void zero_kernel() {
    int i = blockIdx.x * blockDim.x + threadIdx.x;
    if (i < N_NODES) { g_cnt[i] = 0; g_cursor[i] = 0; }
}
__global__ void hist_kernel(const int* __restrict__ dst, int E) {
    int e = blockIdx.x * blockDim.x + threadIdx.x;
    if (e < E) atomicAdd(&g_cnt[dst[e]], 1);
}
__global__ void scan1_kernel() {
    __shared__ int sh[SCAN_B];
    int t = threadIdx.x;
    int i = blockIdx.x * SCAN_B + t;
    int v = (i < N_NODES) ? g_cnt[i] : 0;
    sh[t] = v;
    __syncthreads();
#pragma unroll
    for (int off = 1; off < SCAN_B; off <<= 1) {
        int add = (t >= off) ? sh[t - off] : 0;
        __syncthreads();
        sh[t] += add;
        __syncthreads();
    }
    if (i < N_NODES) g_rowptr[i] = sh[t] - v;
    if (t == SCAN_B - 1) g_blocksum[blockIdx.x] = sh[t];
}
__global__ void scan2_kernel() {
    __shared__ int sh[256];
    int t = threadIdx.x;
    int v = (t < SCAN_NB) ? g_blocksum[t] : 0;
    sh[t] = v;
    __syncthreads();
#pragma unroll
    for (int off = 1; off < 256; off <<= 1) {
        int add = (t >= off) ? sh[t - off] : 0;
        __syncthreads();
        sh[t] += add;
        __syncthreads();
    }
    if (t < SCAN_NB) g_blocksum[t] = sh[t] - v;
}
__global__ void scan3_kernel() {
    int i = blockIdx.x * blockDim.x + threadIdx.x;
    if (i < N_NODES) g_rowptr[i] += g_blocksum[i / SCAN_B];
}
__global__ void scatter_kernel(const int* __restrict__ src,
                               const int* __restrict__ dst, int E) {
    int e = blockIdx.x * blockDim.x + threadIdx.x;
    if (e < E) {
        int d = dst[e];
        int pos = g_rowptr[d] + atomicAdd(&g_cursor[d], 1);
        g_ssrc[pos] = src[e];
    }
}

// ================= fused 4-matrix GEMM ======================================
// {k,q,v,skip} = X @ {Wk,Wq,Wv,Ws}(+b). BM=64, BN=64 (half-matrix per
// blockIdx.y of 8). 128 threads, thread tile 4 rows x 8 cols, X register-
// cached. k,skip -> fp32; q,v -> fp16 packed rows in g_qvh.
#define GBM 64
#define XCH 32
#define XST 36

__global__ void gemm4_kernel(const float* __restrict__ X,
                             const float* __restrict__ Wk,
                             const float* __restrict__ Wq,
                             const float* __restrict__ Wv,
                             const float* __restrict__ Ws,
                             const float* __restrict__ bias,
                             int M) {
    __shared__ float Wsm[128 * 64];
    __shared__ float Xs[GBM * XST];

    const float* Xp = X ? X : g_x;

    const int m0   = blockIdx.x * GBM;
    const int bn   = blockIdx.y;
    const int mat  = bn >> 1;
    const int noff = (bn & 1) * 64;

    const float* W = (mat == 0) ? Wk : (mat == 1) ? Wq : (mat == 2) ? Wv : Ws;

    const int tid = threadIdx.x;        // 0..127
    const int ty  = tid >> 3;           // 0..15 -> rows ty + 16*i
    const int tx  = tid & 7;            // 0..7  -> cols tx*8 .. tx*8+7

    // Load W half [128][64] (float4, coalesced)
    for (int i = tid; i < 128 * 16; i += 128) {
        int k = i >> 4, n4 = i & 15;
        *(float4*)(Wsm + k * 64 + n4 * 4) =
            *(const float4*)(W + k * 128 + noff + n4 * 4);
    }

    unsigned long long acc[4][4];
#pragma unroll
    for (int i = 0; i < 4; i++)
#pragma unroll
        for (int j = 0; j < 4; j++) acc[i][j] = 0ULL;

    for (int ch = 0; ch < 128 / XCH; ch++) {
        __syncthreads();
        for (int i = tid; i < GBM * (XCH / 4); i += 128) {
            int r = i >> 3, c4 = i & 7;
            float4 val = make_float4(0.f, 0.f, 0.f, 0.f);
            if (m0 + r < M)
                val = *(const float4*)(Xp + (size_t)(m0 + r) * 128 + ch * XCH + c4 * 4);
            *(float4*)(Xs + r * XST + c4 * 4) = val;
        }
        __syncthreads();

#pragma unroll
        for (int kk4 = 0; kk4 < XCH / 4; kk4++) {
            float xa[4][4];
#pragma unroll
            for (int i = 0; i < 4; i++) {
                float4 xv = *(const float4*)(Xs + (ty + 16 * i) * XST + kk4 * 4);
                xa[i][0] = xv.x; xa[i][1] = xv.y; xa[i][2] = xv.z; xa[i][3] = xv.w;
            }
#pragma unroll
            for (int j = 0; j < 4; j++) {
                const unsigned long long* wp = (const unsigned long long*)
                    (Wsm + (ch * XCH + kk4 * 4 + j) * 64 + tx * 8);
                unsigned long long b0 = wp[0], b1 = wp[1], b2 = wp[2], b3 = wp[3];
#pragma unroll
                for (int i = 0; i < 4; i++) {
                    unsigned long long aa = pack2(xa[i][j]);
                    acc[i][0] = fma2(aa, b0, acc[i][0]);
                    acc[i][1] = fma2(aa, b1, acc[i][1]);
                    acc[i][2] = fma2(aa, b2, acc[i][2]);
                    acc[i][3] = fma2(aa, b3, acc[i][3]);
                }
            }
        }
    }

    const int col = noff + tx * 8;
    float bb[8];
#pragma unroll
    for (int j = 0; j < 8; j++) bb[j] = 0.f;
    if (mat == 3) {
#pragma unroll
        for (int j = 0; j < 8; j++) bb[j] = bias[col + j];
    }
#pragma unroll
    for (int i = 0; i < 4; i++) {
        int r = m0 + ty + 16 * i;
        if (r >= M) continue;
        float o[8];
        unpack2(acc[i][0], o[0], o[1]);
        unpack2(acc[i][1], o[2], o[3]);
        unpack2(acc[i][2], o[4], o[5]);
        unpack2(acc[i][3], o[6], o[7]);
        if (mat == 0 || mat == 3) {
            float* Op = (mat == 0) ? g_k : g_agg;
            *(float4*)(Op + (size_t)r * 128 + col) =
                make_float4(o[0] + bb[0], o[1] + bb[1], o[2] + bb[2], o[3] + bb[3]);
            *(float4*)(Op + (size_t)r * 128 + col + 4) =
                make_float4(o[4] + bb[4], o[5] + bb[5], o[6] + bb[6], o[7] + bb[7]);
        } else {
            // q -> halves [0,128), v -> halves [128,256) of the packed row
            __half2 h0 = __floats2half2_rn(o[0], o[1]);
            __half2 h1 = __floats2half2_rn(o[2], o[3]);
            __half2 h2 = __floats2half2_rn(o[4], o[5]);
            __half2 h3 = __floats2half2_rn(o[6], o[7]);
            uint4 u = make_uint4(*(uint32_t*)&h0, *(uint32_t*)&h1,
                                 *(uint32_t*)&h2, *(uint32_t*)&h3);
            size_t hoff = (size_t)r * 256 + ((mat == 2) ? 128 : 0) + col;
            *(uint4*)(g_qvh + hoff) = u;
        }
    }
}

// ================= per-dst aggregation (CSR, no atomics, fp16 gathers) ======
// One warp per destination node; lane j handles features 4j..4j+3.
__device__ __forceinline__ void edge_accum(int s, int lane, const float4& kk,
                                           float4& acc) {
    const uint2* qp = (const uint2*)(g_qvh + (size_t)s * 256) + lane;
    const uint2* vp = (const uint2*)(g_qvh + (size_t)s * 256 + 128) + lane;
    uint2 qu = *qp;
    uint2 vu = *vp;
    float2 q01 = __half22float2(*(const __half2*)&qu.x);
    float2 q23 = __half22float2(*(const __half2*)&qu.y);
    float2 v01 = __half22float2(*(const __half2*)&vu.x);
    float2 v23 = __half22float2(*(const __half2*)&vu.y);
    acc.x += v01.x * sigf(kk.x + q01.x);
    acc.y += v01.y * sigf(kk.y + q01.y);
    acc.z += v23.x * sigf(kk.z + q23.x);
    acc.w += v23.y * sigf(kk.w + q23.y);
}

__global__ void agg_kernel(int relu_flag) {
    int w = (blockIdx.x * blockDim.x + threadIdx.x) >> 5;
    int lane = threadIdx.x & 31;
    if (w >= N_NODES) return;

    float4 kk = *(const float4*)(g_k + (size_t)w * 128 + lane * 4);
    int start = g_rowptr[w];
    int len   = g_cnt[w];

    float4 acc = make_float4(0.f, 0.f, 0.f, 0.f);
    int i = 0;
    for (; i + 4 <= len; i += 4) {
        int s0 = g_ssrc[start + i];
        int s1 = g_ssrc[start + i + 1];
        int s2 = g_ssrc[start + i + 2];
        int s3 = g_ssrc[start + i + 3];
        edge_accum(s0, lane, kk, acc);
        edge_accum(s1, lane, kk, acc);
        edge_accum(s2, lane, kk, acc);
        edge_accum(s3, lane, kk, acc);
    }
    for (; i < len; i++)
        edge_accum(g_ssrc[start + i], lane, kk, acc);

    float4 skip = *(const float4*)(g_agg + (size_t)w * 128 + lane * 4);
    float4 r = make_float4(skip.x + acc.x, skip.y + acc.y,
                           skip.z + acc.z, skip.w + acc.w);
    if (relu_flag) {
        r.x = fmaxf(r.x, 0.f); r.y = fmaxf(r.y, 0.f);
        r.z = fmaxf(r.z, 0.f); r.w = fmaxf(r.w, 0.f);
    }
    *(float4*)(g_x + (size_t)w * 128 + lane * 4) = r;
}

// ================= layer 3 (Dout=1) =========================================
__global__ void gemm3_kernel(const float* __restrict__ Wk,
                             const float* __restrict__ Wq,
                             const float* __restrict__ Wv,
                             const float* __restrict__ Ws,
                             const float* __restrict__ bias,
                             float* __restrict__ out,
                             int Nn) {
    int warp = (blockIdx.x * blockDim.x + threadIdx.x) >> 5;
    int lane = threadIdx.x & 31;
    if (warp >= Nn) return;

    float4 xv = *(const float4*)(g_x + (size_t)warp * 128 + lane * 4);
    float4 wk = ((const float4*)Wk)[lane];
    float4 wq = ((const float4*)Wq)[lane];
    float4 wv = ((const float4*)Wv)[lane];
    float4 ws = ((const float4*)Ws)[lane];

    float dk = xv.x * wk.x + xv.y * wk.y + xv.z * wk.z + xv.w * wk.w;
    float dq = xv.x * wq.x + xv.y * wq.y + xv.z * wq.z + xv.w * wq.w;
    float dv = xv.x * wv.x + xv.y * wv.y + xv.z * wv.z + xv.w * wv.w;
    float ds = xv.x * ws.x + xv.y * ws.y + xv.z * ws.z + xv.w * ws.w;

#pragma unroll
    for (int o = 16; o; o >>= 1) {
        dk += __shfl_xor_sync(0xFFFFFFFFu, dk, o);
        dq += __shfl_xor_sync(0xFFFFFFFFu, dq, o);
        dv += __shfl_xor_sync(0xFFFFFFFFu, dv, o);
        ds += __shfl_xor_sync(0xFFFFFFFFu, ds, o);
    }
    if (lane == 0) {
        g_k3[warp] = dk;
        g_q3[warp] = dq;
        g_v3[warp] = dv;
        out[warp]  = ds + bias[0];
    }
}

__global__ void edge3_kernel(float* __restrict__ out) {
    int d = blockIdx.x * blockDim.x + threadIdx.x;
    if (d >= N_NODES) return;
    int start = g_rowptr[d];
    int len   = g_cnt[d];
    float kd = g_k3[d];
    float s = 0.f;
    for (int i = 0; i < len; i++) {
        int sn = g_ssrc[start + i];
        s += g_v3[sn] * sigf(kd + g_q3[sn]);
    }
    out[d] += s;
}

// ================= launch ===================================================
extern "C" void kernel_launch(void* const* d_in, const int* in_sizes, int n_in,
                              void* d_out, int out_size) {
    const float* x  = (const float*)d_in[0];
    const int*   ei = (const int*)d_in[1];
    const int E = in_sizes[1] / 2;
    const int N = in_sizes[0] / D_FEAT;
    const int* src = ei;
    const int* dst = ei + E;

    const float* Wk1 = (const float*)d_in[2];
    const float* Wq1 = (const float*)d_in[3];
    const float* Wv1 = (const float*)d_in[4];
    const float* Ws1 = (const float*)d_in[5];
    const float* b1  = (const float*)d_in[6];
    const float* Wk2 = (const float*)d_in[7];
    const float* Wq2 = (const float*)d_in[8];
    const float* Wv2 = (const float*)d_in[9];
    const float* Ws2 = (const float*)d_in[10];
    const float* b2  = (const float*)d_in[11];
    const float* Wk3 = (const float*)d_in[12];
    const float* Wq3 = (const float*)d_in[13];
    const float* Wv3 = (const float*)d_in[14];
    const float* Ws3 = (const float*)d_in[15];
    const float* b3  = (const float*)d_in[16];

    float* out = (float*)d_out;

    dim3 gemm_grid((N + GBM - 1) / GBM, 8);
    int nblk256 = (N_NODES + 255) / 256;
    int eblk256 = (E + 255) / 256;
    int agg_blocks  = (N + 7) / 8;
    int gemv_blocks = (N + 7) / 8;

    // ---- build dst-sorted CSR (once per call, reused by 3 edge passes) ----
    zero_kernel<<<nblk256, 256>>>();
    hist_kernel<<<eblk256, 256>>>(dst, E);
    scan1_kernel<<<SCAN_NB, SCAN_B>>>();
    scan2_kernel<<<1, 256>>>();
    scan3_kernel<<<nblk256, 256>>>();
    scatter_kernel<<<eblk256, 256>>>(src, dst, E);

    // ---- layer 1 ----
    gemm4_kernel<<<gemm_grid, 128>>>(x, Wk1, Wq1, Wv1, Ws1, b1, N);
    agg_kernel<<<agg_blocks, 256>>>(1);

    // ---- layer 2 (X = nullptr -> kernel reads g_x device-side) ----
    gemm4_kernel<<<gemm_grid, 128>>>(nullptr, Wk2, Wq2, Wv2, Ws2, b2, N);
    agg_kernel<<<agg_blocks, 256>>>(1);

    // ---- layer 3 (Dout=1) ----
    gemm3_kernel<<<gemv_blocks, 256>>>(Wk3, Wq3, Wv3, Ws3, b3, out, N);
    edge3_kernel<<<nblk256, 256>>>(out);
}